// round 6
// baseline (speedup 1.0000x reference)
#include <cuda_runtime.h>
#include <cuda_bf16.h>
#include <cstdint>

#define B_   16
#define V_   20000
#define D_   256
#define H_   256
#define EPS_ 1e-5f

// ======================= helpers =======================
__device__ __forceinline__ uint32_t smem_u32(const void* p) {
    uint32_t a;
    asm("{ .reg .u64 t; cvta.to.shared.u64 t, %1; cvt.u32.u64 %0, t; }" : "=r"(a) : "l"(p));
    return a;
}
__device__ __forceinline__ void ldsm4(uint32_t* r, uint32_t addr) {
    asm volatile("ldmatrix.sync.aligned.m8n8.x4.shared.b16 {%0,%1,%2,%3}, [%4];"
        : "=r"(r[0]), "=r"(r[1]), "=r"(r[2]), "=r"(r[3]) : "r"(addr));
}
__device__ __forceinline__ void ldsm4t(uint32_t* r, uint32_t addr) {
    asm volatile("ldmatrix.sync.aligned.m8n8.x4.trans.shared.b16 {%0,%1,%2,%3}, [%4];"
        : "=r"(r[0]), "=r"(r[1]), "=r"(r[2]), "=r"(r[3]) : "r"(addr));
}
__device__ __forceinline__ void mma_bf16(float* c, const uint32_t* a, const uint32_t* b) {
    asm volatile("mma.sync.aligned.m16n8k16.row.col.f32.bf16.bf16.f32 "
        "{%0,%1,%2,%3}, {%4,%5,%6,%7}, {%8,%9}, {%0,%1,%2,%3};"
        : "+f"(c[0]), "+f"(c[1]), "+f"(c[2]), "+f"(c[3])
        : "r"(a[0]), "r"(a[1]), "r"(a[2]), "r"(a[3]), "r"(b[0]), "r"(b[1]));
}
__device__ __forceinline__ uint32_t pack2bf16(float a, float b) {
    unsigned short ua = __bfloat16_as_ushort(__float2bfloat16(a));
    unsigned short ub = __bfloat16_as_ushort(__float2bfloat16(b));
    return ((uint32_t)ub << 16) | ua;
}
__device__ __forceinline__ void cp16(uint32_t dst, const void* src) {
    asm volatile("cp.async.cg.shared.global [%0], [%1], 16;" :: "r"(dst), "l"(src));
}
#define CP_COMMIT() asm volatile("cp.async.commit_group;" ::: "memory")
#define CP_WAIT(n)  asm volatile("cp.async.wait_group %0;" :: "n"(n) : "memory")
#define TANH(d, x)  asm("tanh.approx.f32 %0, %1;" : "=f"(d) : "f"(x))

// ======================= scratch =======================
__device__ float g_pht[H_ * B_];          // [h][b]
__device__ float g_scores[B_ * V_];       // [b][v]
__device__ float g_stats[2 * B_];
// split weights, NO transpose: [mat(2)][split(2)][k(256)][n(256)] bf16
__device__ __align__(16) __nv_bfloat16 g_Bs[2 * 2 * 256 * 256];

// ---------------- prep: split weights hi/lo ----------------
__global__ void k_prep_w(const float* __restrict__ Wa, const float* __restrict__ W1)
{
    int mat = blockIdx.x >> 4;
    int kg  = blockIdx.x & 15;
    int n   = threadIdx.x;
    const float* W = mat ? (W1 + (size_t)D_ * H_) : Wa;   // [k][n]
    __nv_bfloat16* dh = g_Bs + (size_t)(mat * 2 + 0) * 65536;
    __nv_bfloat16* dl = g_Bs + (size_t)(mat * 2 + 1) * 65536;
    #pragma unroll 4
    for (int kp = 0; kp < 16; kp++) {
        int k = kg * 16 + kp;
        float v = W[(size_t)k * 256 + n];
        __nv_bfloat16 h = __float2bfloat16(v);
        dh[(size_t)k * 256 + n] = h;
        dl[(size_t)k * 256 + n] = __float2bfloat16(v - __bfloat162float(h));
    }
}

// ---------------- patient path: proj + LN + head ----------------
__global__ void k_patient(const float* __restrict__ pe,
                          const float* __restrict__ Wp,
                          const float* __restrict__ bp,
                          const float* __restrict__ gp,
                          const float* __restrict__ betap,
                          const float* __restrict__ W1,
                          const float* __restrict__ b1)
{
    int b = blockIdx.x, d = threadIdx.x;
    __shared__ float s_pe[D_], s_p[D_];
    s_pe[d] = pe[b * D_ + d];
    __syncthreads();
    float acc = bp[d];
    #pragma unroll 8
    for (int k = 0; k < D_; k++) acc = fmaf(s_pe[k], Wp[k * D_ + d], acc);
    float s1 = acc, s2 = acc * acc;
    #pragma unroll
    for (int o = 16; o; o >>= 1) {
        s1 += __shfl_xor_sync(0xffffffffu, s1, o);
        s2 += __shfl_xor_sync(0xffffffffu, s2, o);
    }
    __shared__ float r1[8], r2[8], bc[2];
    int w = d >> 5, l = d & 31;
    if (l == 0) { r1[w] = s1; r2[w] = s2; }
    __syncthreads();
    if (d == 0) {
        float t1 = 0.f, t2 = 0.f;
        #pragma unroll
        for (int i = 0; i < 8; i++) { t1 += r1[i]; t2 += r2[i]; }
        float mean = t1 * (1.0f / D_);
        float var  = t2 * (1.0f / D_) - mean * mean;
        bc[0] = mean; bc[1] = rsqrtf(var + EPS_);
    }
    __syncthreads();
    s_p[d] = (acc - bc[0]) * bc[1] * gp[d] + betap[d];
    __syncthreads();
    float acc2 = b1[d];
    #pragma unroll 8
    for (int k = 0; k < D_; k++) acc2 = fmaf(s_p[k], W1[k * H_ + d], acc2);
    g_pht[d * B_ + b] = acc2;
}

// ---------------- fused HMMA + LN + score kernel ----------------
static constexpr uint32_t A_HI  = 0;        // 32768
static constexpr uint32_t A_LO  = 32768;    // 32768
static constexpr uint32_t B_B0  = 65536;
static constexpr uint32_t B_STR = 16896;    // per stage (hi 8448 + lo 8448)
static constexpr uint32_t B_LOO = 8448;
static constexpr uint32_t P_BA  = 99328;    // ba; overwritten by W2 in epilogue
static constexpr uint32_t P_GA  = 100352;
static constexpr uint32_t P_BE  = 101376;
static constexpr uint32_t S_SUM = 102400;
static constexpr uint32_t S_SQ  = 103424;
static constexpr uint32_t S_MRS = 104448;
static constexpr uint32_t SMEM_SZ = 104960;

__global__ __launch_bounds__(256, 2)
void k_fused(const float* __restrict__ atc4,
             const float* __restrict__ ba,
             const float* __restrict__ ga,
             const float* __restrict__ betaa,
             const float* __restrict__ W2,
             const float* __restrict__ b2)
{
    extern __shared__ __align__(16) unsigned char smem[];
    uint32_t sb = smem_u32(smem);
    int tid = threadIdx.x;
    int wid = tid >> 5;
    int l   = tid & 31;
    int wm  = wid >> 2;          // 0..1 : rows wm*32..+31
    int wn  = wid & 3;           // 0..3 : cols wn*64..+63
    int quad = l >> 2;
    int tid4 = l & 3;
    int m0 = blockIdx.x * 64;

    auto issue = [&](int t) {
        int phase = t >> 4, c = t & 15;
        uint32_t bb = sb + B_B0 + (uint32_t)(t & 1) * B_STR;
        const __nv_bfloat16* bh = g_Bs + (size_t)(phase * 2) * 65536 + (size_t)c * 16 * 256;
        const __nv_bfloat16* bl = bh + 65536;
        #pragma unroll
        for (int it = 0; it < 2; it++) {
            int id = it * 256 + tid;
            int k = id >> 5, u = id & 31;
            uint32_t dst = (uint32_t)k * 528 + (uint32_t)u * 16;
            cp16(bb + dst,         bh + (size_t)k * 256 + u * 8);
            cp16(bb + B_LOO + dst, bl + (size_t)k * 256 + u * 8);
        }
        CP_COMMIT();
    };

    issue(0);
    issue(1);

    ((float*)(smem + P_BA))[tid] = ba[tid];
    ((float*)(smem + P_GA))[tid] = ga[tid];
    ((float*)(smem + P_BE))[tid] = betaa[tid];

    // ---- convert atc4 tile -> bf16 hi/lo into swizzled A smem ----
    #pragma unroll
    for (int it = 0; it < 8; it++) {
        int id = it * 256 + tid;
        int row = id >> 5, u = id & 31;
        int gr = m0 + row;
        float f[8];
        if (gr < V_) {
            float4 v0 = *(const float4*)&atc4[(size_t)gr * 256 + u * 8];
            float4 v1 = *(const float4*)&atc4[(size_t)gr * 256 + u * 8 + 4];
            f[0]=v0.x; f[1]=v0.y; f[2]=v0.z; f[3]=v0.w;
            f[4]=v1.x; f[5]=v1.y; f[6]=v1.z; f[7]=v1.w;
        } else {
            #pragma unroll
            for (int i = 0; i < 8; i++) f[i] = 0.f;
        }
        float hf[8], lf[8];
        #pragma unroll
        for (int i = 0; i < 8; i++) {
            hf[i] = __bfloat162float(__float2bfloat16(f[i]));
            lf[i] = f[i] - hf[i];
        }
        uint4 hp, lp;
        hp.x = pack2bf16(hf[0], hf[1]); hp.y = pack2bf16(hf[2], hf[3]);
        hp.z = pack2bf16(hf[4], hf[5]); hp.w = pack2bf16(hf[6], hf[7]);
        lp.x = pack2bf16(lf[0], lf[1]); lp.y = pack2bf16(lf[2], lf[3]);
        lp.z = pack2bf16(lf[4], lf[5]); lp.w = pack2bf16(lf[6], lf[7]);
        uint32_t off = (uint32_t)row * 512 + (((uint32_t)u ^ ((uint32_t)row & 7)) << 4);
        *(uint4*)(smem + A_HI + off) = hp;
        *(uint4*)(smem + A_LO + off) = lp;
    }

    int ar = wm * 32 + (l & 15);
    uint32_t arx = (uint32_t)(ar & 7);
    uint32_t a_base = sb + A_HI + (uint32_t)ar * 512;
    uint32_t kusel = (uint32_t)((l >> 4) & 1);
    uint32_t b_lane = (uint32_t)(l & 15) * 528 + (uint32_t)(wn * 64 + ((l >> 4) & 1) * 8) * 2;

    float acc[8][2][4];
    #pragma unroll
    for (int nb = 0; nb < 8; nb++)
        #pragma unroll
        for (int mb = 0; mb < 2; mb++)
            #pragma unroll
            for (int i = 0; i < 4; i++) acc[nb][mb][i] = 0.f;

    #pragma unroll 1
    for (int t = 0; t < 32; t++) {
        int c = t & 15;
        uint32_t bb = sb + B_B0 + (uint32_t)(t & 1) * B_STR;

        if (t == 31) { CP_WAIT(0); } else { CP_WAIT(1); }
        __syncthreads();

        if (t == 31) {
            // buf0 is dead (last read at t=30): prefetch pht into it, overlapping
            // the final mma chunk. W2 overwrites dead ba smem.
            uint32_t pb = sb + B_B0;
            int h = tid;
            #pragma unroll
            for (int b4 = 0; b4 < 4; b4++) {
                uint32_t dst = pb + (uint32_t)h * 64
                             + ((((uint32_t)b4 + ((uint32_t)h >> 1)) & 3) << 4);
                cp16(dst, g_pht + h * 16 + b4 * 4);
            }
            CP_COMMIT();
            ((float*)(smem + P_BA))[tid] = W2[tid];
        }

        uint32_t ku = (uint32_t)(c * 2) + kusel;
        uint32_t aa = a_base + ((ku ^ arx) << 4);
        uint32_t ah0[4], ah1[4], al0[4], al1[4];
        ldsm4(ah0, aa);
        ldsm4(ah1, aa + 8192);
        ldsm4(al0, aa + 32768);
        ldsm4(al1, aa + 40960);
        #pragma unroll
        for (int p = 0; p < 4; p++) {
            uint32_t bo = bb + b_lane + (uint32_t)(p * 32);
            uint32_t rh[4], rl[4];
            ldsm4t(rh, bo);
            ldsm4t(rl, bo + B_LOO);
            #pragma unroll
            for (int q = 0; q < 2; q++) {
                int nb = p * 2 + q;
                mma_bf16(acc[nb][0], ah0, &rh[q * 2]);
                mma_bf16(acc[nb][0], ah0, &rl[q * 2]);
                mma_bf16(acc[nb][0], al0, &rh[q * 2]);
                mma_bf16(acc[nb][1], ah1, &rh[q * 2]);
                mma_bf16(acc[nb][1], ah1, &rl[q * 2]);
                mma_bf16(acc[nb][1], al1, &rh[q * 2]);
            }
        }

        __syncthreads();
        if (t < 30) issue(t + 2);

        if (t == 15) {
            // ---- row LN; re-split into A smem ----
            const float* s_ba = (const float*)(smem + P_BA);
            const float* s_ga = (const float*)(smem + P_GA);
            const float* s_be = (const float*)(smem + P_BE);
            float* psum = (float*)(smem + S_SUM);
            float* psq  = (float*)(smem + S_SQ);
            float* mrs  = (float*)(smem + S_MRS);

            #pragma unroll
            for (int mb = 0; mb < 2; mb++) {
                #pragma unroll
                for (int half = 0; half < 2; half++) {
                    float s1 = 0.f, s2 = 0.f;
                    #pragma unroll
                    for (int nb = 0; nb < 8; nb++) {
                        int col = wn * 64 + nb * 8 + tid4 * 2;
                        float x0 = acc[nb][mb][half * 2 + 0] + s_ba[col];
                        float x1 = acc[nb][mb][half * 2 + 1] + s_ba[col + 1];
                        s1 += x0 + x1;
                        s2 = fmaf(x0, x0, fmaf(x1, x1, s2));
                    }
                    s1 += __shfl_xor_sync(0xffffffffu, s1, 1);
                    s2 += __shfl_xor_sync(0xffffffffu, s2, 1);
                    s1 += __shfl_xor_sync(0xffffffffu, s1, 2);
                    s2 += __shfl_xor_sync(0xffffffffu, s2, 2);
                    if (tid4 == 0) {
                        int row = wm * 32 + mb * 16 + quad + half * 8;
                        psum[row * 4 + wn] = s1;
                        psq[row * 4 + wn]  = s2;
                    }
                }
            }
            __syncthreads();
            if (tid < 64) {
                float s1 = psum[tid * 4] + psum[tid * 4 + 1] + psum[tid * 4 + 2] + psum[tid * 4 + 3];
                float s2 = psq[tid * 4] + psq[tid * 4 + 1] + psq[tid * 4 + 2] + psq[tid * 4 + 3];
                float mean = s1 * (1.0f / 256.0f);
                float var  = s2 * (1.0f / 256.0f) - mean * mean;
                mrs[tid * 2]     = mean;
                mrs[tid * 2 + 1] = rsqrtf(var + EPS_);
            }
            __syncthreads();
            #pragma unroll
            for (int mb = 0; mb < 2; mb++) {
                #pragma unroll
                for (int half = 0; half < 2; half++) {
                    int row = wm * 32 + mb * 16 + quad + half * 8;
                    float mean = mrs[row * 2], rstd = mrs[row * 2 + 1];
                    #pragma unroll
                    for (int nb = 0; nb < 8; nb++) {
                        int col = wn * 64 + nb * 8 + tid4 * 2;
                        float x0 = acc[nb][mb][half * 2 + 0] + s_ba[col];
                        float x1 = acc[nb][mb][half * 2 + 1] + s_ba[col + 1];
                        float v0 = (x0 - mean) * rstd * s_ga[col] + s_be[col];
                        float v1 = (x1 - mean) * rstd * s_ga[col + 1] + s_be[col + 1];
                        float h0 = __bfloat162float(__float2bfloat16(v0));
                        float h1 = __bfloat162float(__float2bfloat16(v1));
                        uint32_t u = (uint32_t)(col >> 3);
                        uint32_t off = (uint32_t)row * 512 + ((u ^ ((uint32_t)row & 7)) << 4)
                                     + (uint32_t)tid4 * 4;
                        *(uint32_t*)(smem + A_HI + off) = pack2bf16(h0, h1);
                        *(uint32_t*)(smem + A_LO + off) = pack2bf16(v0 - h0, v1 - h1);
                    }
                }
            }
            #pragma unroll
            for (int nb = 0; nb < 8; nb++)
                #pragma unroll
                for (int mb = 0; mb < 2; mb++)
                    #pragma unroll
                    for (int i = 0; i < 4; i++) acc[nb][mb][i] = 0.f;
            __syncthreads();
        }
    }

    // ================= score epilogue =================
    // acc holds ah for this CTA's 64 rows. pht in buf0 (swizzled), W2 in P_BA.
    CP_WAIT(0);
    __syncthreads();

    const float* s_w2v = (const float*)(smem + P_BA);
    float b2v = b2[0];
    float* red = (float*)smem;          // reuse A region: [row][l16][b] = 64KB
    int l16 = wn * 4 + tid4;

    #pragma unroll
    for (int mb = 0; mb < 2; mb++) {
        #pragma unroll
        for (int half = 0; half < 2; half++) {
            int row = wm * 32 + mb * 16 + quad + half * 8;
            float part[16];
            #pragma unroll
            for (int b = 0; b < 16; b++) part[b] = 0.f;
            #pragma unroll
            for (int nb = 0; nb < 8; nb++) {
                #pragma unroll
                for (int e = 0; e < 2; e++) {
                    int h = wn * 64 + nb * 8 + tid4 * 2 + e;
                    float a  = acc[nb][mb][half * 2 + e];
                    float w2 = s_w2v[h];
                    #pragma unroll
                    for (int b4 = 0; b4 < 4; b4++) {
                        uint32_t off = B_B0 + (uint32_t)h * 64
                                     + ((((uint32_t)b4 + ((uint32_t)h >> 1)) & 3) << 4);
                        float4 p = *(const float4*)(smem + off);
                        float th;
                        TANH(th, a + p.x); part[b4 * 4 + 0] = fmaf(w2, th, part[b4 * 4 + 0]);
                        TANH(th, a + p.y); part[b4 * 4 + 1] = fmaf(w2, th, part[b4 * 4 + 1]);
                        TANH(th, a + p.z); part[b4 * 4 + 2] = fmaf(w2, th, part[b4 * 4 + 2]);
                        TANH(th, a + p.w); part[b4 * 4 + 3] = fmaf(w2, th, part[b4 * 4 + 3]);
                    }
                }
            }
            float4* dst = (float4*)&red[row * 256 + l16 * 16];
            dst[0] = make_float4(part[0],  part[1],  part[2],  part[3]);
            dst[1] = make_float4(part[4],  part[5],  part[6],  part[7]);
            dst[2] = make_float4(part[8],  part[9],  part[10], part[11]);
            dst[3] = make_float4(part[12], part[13], part[14], part[15]);
        }
    }
    __syncthreads();
    {
        int row = tid >> 2, bq = (tid & 3) * 4;
        const float* src = &red[row * 256 + bq];
        float4 s = *(const float4*)src;
        #pragma unroll
        for (int ll = 1; ll < 16; ll++) {
            float4 v = *(const float4*)(src + ll * 16);
            s.x += v.x; s.y += v.y; s.z += v.z; s.w += v.w;
        }
        int grow = m0 + row;
        if (grow < V_) {
            g_scores[(size_t)(bq + 0) * V_ + grow] = s.x + b2v;
            g_scores[(size_t)(bq + 1) * V_ + grow] = s.y + b2v;
            g_scores[(size_t)(bq + 2) * V_ + grow] = s.z + b2v;
            g_scores[(size_t)(bq + 3) * V_ + grow] = s.w + b2v;
        }
    }
}

// ---------------- per-b mean/rstd over V ----------------
__global__ void k_reduce()
{
    int b = blockIdx.x, t = threadIdx.x;
    const float4* row = (const float4*)&g_scores[(size_t)b * V_];
    float s1 = 0.f, s2 = 0.f;
    #pragma unroll 4
    for (int v = t; v < V_ / 4; v += 256) {
        float4 x = row[v];
        s1 += x.x + x.y + x.z + x.w;
        s2 = fmaf(x.x, x.x, fmaf(x.y, x.y, fmaf(x.z, x.z, fmaf(x.w, x.w, s2))));
    }
    #pragma unroll
    for (int o = 16; o; o >>= 1) {
        s1 += __shfl_xor_sync(0xffffffffu, s1, o);
        s2 += __shfl_xor_sync(0xffffffffu, s2, o);
    }
    __shared__ float r1[8], r2[8];
    int w = t >> 5, ll = t & 31;
    if (ll == 0) { r1[w] = s1; r2[w] = s2; }
    __syncthreads();
    if (t == 0) {
        float t1 = 0.f, t2 = 0.f;
        #pragma unroll
        for (int i = 0; i < 8; i++) { t1 += r1[i]; t2 += r2[i]; }
        float mean = t1 * (1.0f / V_);
        float var  = t2 * (1.0f / V_) - mean * mean;
        g_stats[2 * b] = mean;
        g_stats[2 * b + 1] = rsqrtf(var + EPS_);
    }
}

__global__ void k_norm(const float* __restrict__ g_pred,
                       const float* __restrict__ b_pred,
                       float* __restrict__ out)
{
    int i = blockIdx.x * 256 + threadIdx.x;
    if (i >= B_ * V_) return;
    int b = i / V_;
    int v = i - b * V_;
    out[i] = (g_scores[i] - g_stats[2 * b]) * g_stats[2 * b + 1] * g_pred[v] + b_pred[v];
}

// ---------------- launch ----------------
extern "C" void kernel_launch(void* const* d_in, const int* in_sizes, int n_in,
                              void* d_out, int out_size)
{
    const float* pe     = (const float*)d_in[0];
    const float* atc4   = (const float*)d_in[1];
    const float* Wp     = (const float*)d_in[2];
    const float* bp     = (const float*)d_in[3];
    const float* gp     = (const float*)d_in[4];
    const float* betap  = (const float*)d_in[5];
    const float* Wa     = (const float*)d_in[6];
    const float* ba     = (const float*)d_in[7];
    const float* ga     = (const float*)d_in[8];
    const float* betaa  = (const float*)d_in[9];
    const float* W1     = (const float*)d_in[10];
    const float* b1     = (const float*)d_in[11];
    const float* W2     = (const float*)d_in[12];
    const float* b2     = (const float*)d_in[13];
    const float* gpred  = (const float*)d_in[14];
    const float* bpred  = (const float*)d_in[15];
    float* out = (float*)d_out;
    (void)in_sizes; (void)n_in; (void)out_size;

    cudaFuncSetAttribute(k_fused, cudaFuncAttributeMaxDynamicSharedMemorySize, SMEM_SZ);

    k_prep_w<<<32, 256>>>(Wa, W1);
    k_patient<<<B_, 256>>>(pe, Wp, bp, gp, betap, W1, b1);

    int tiles = (V_ + 63) / 64;   // 313
    k_fused<<<tiles, 256, SMEM_SZ>>>(atc4, ba, ga, betaa, W2, b2);

    k_reduce<<<B_, 256>>>();
    k_norm<<<(B_ * V_ + 255) / 256, 256>>>(gpred, bpred, out);
}

// round 7
// speedup vs baseline: 1.5402x; 1.5402x over previous
#include <cuda_runtime.h>
#include <cuda_bf16.h>
#include <cuda_fp16.h>
#include <cstdint>

#define B_   16
#define V_   20000
#define D_   256
#define H_   256
#define EPS_ 1e-5f

// ======================= helpers =======================
__device__ __forceinline__ uint32_t smem_u32(const void* p) {
    uint32_t a;
    asm("{ .reg .u64 t; cvta.to.shared.u64 t, %1; cvt.u32.u64 %0, t; }" : "=r"(a) : "l"(p));
    return a;
}
__device__ __forceinline__ void ldsm4(uint32_t* r, uint32_t addr) {
    asm volatile("ldmatrix.sync.aligned.m8n8.x4.shared.b16 {%0,%1,%2,%3}, [%4];"
        : "=r"(r[0]), "=r"(r[1]), "=r"(r[2]), "=r"(r[3]) : "r"(addr));
}
__device__ __forceinline__ void ldsm4t(uint32_t* r, uint32_t addr) {
    asm volatile("ldmatrix.sync.aligned.m8n8.x4.trans.shared.b16 {%0,%1,%2,%3}, [%4];"
        : "=r"(r[0]), "=r"(r[1]), "=r"(r[2]), "=r"(r[3]) : "r"(addr));
}
__device__ __forceinline__ void mma_bf16(float* c, const uint32_t* a, const uint32_t* b) {
    asm volatile("mma.sync.aligned.m16n8k16.row.col.f32.bf16.bf16.f32 "
        "{%0,%1,%2,%3}, {%4,%5,%6,%7}, {%8,%9}, {%0,%1,%2,%3};"
        : "+f"(c[0]), "+f"(c[1]), "+f"(c[2]), "+f"(c[3])
        : "r"(a[0]), "r"(a[1]), "r"(a[2]), "r"(a[3]), "r"(b[0]), "r"(b[1]));
}
__device__ __forceinline__ uint32_t pack2bf16(float a, float b) {
    unsigned short ua = __bfloat16_as_ushort(__float2bfloat16(a));
    unsigned short ub = __bfloat16_as_ushort(__float2bfloat16(b));
    return ((uint32_t)ub << 16) | ua;
}
__device__ __forceinline__ void cp16(uint32_t dst, const void* src) {
    asm volatile("cp.async.cg.shared.global [%0], [%1], 16;" :: "r"(dst), "l"(src));
}
#define CP_COMMIT() asm volatile("cp.async.commit_group;" ::: "memory")
#define CP_WAIT(n)  asm volatile("cp.async.wait_group %0;" :: "n"(n) : "memory")

// ======================= scratch =======================
__device__ float g_pht[H_ * B_];          // [h][b]
__device__ float g_ah[V_ * D_];
__device__ float g_scores[B_ * V_];
__device__ float g_stats[2 * B_];
// split weights, NO transpose: [mat(2)][split(2)][k(256)][n(256)] bf16
__device__ __align__(16) __nv_bfloat16 g_Bs[2 * 2 * 256 * 256];

// ---------------- prep (blocks 0..31) + patient (blocks 32..47) ----------------
__global__ void k_prep(const float* __restrict__ Wa, const float* __restrict__ W1,
                       const float* __restrict__ pe, const float* __restrict__ Wp,
                       const float* __restrict__ bp, const float* __restrict__ gp,
                       const float* __restrict__ betap, const float* __restrict__ b1)
{
    if (blockIdx.x < 32) {
        int mat = blockIdx.x >> 4;
        int kg  = blockIdx.x & 15;
        int n   = threadIdx.x;
        const float* W = mat ? (W1 + (size_t)D_ * H_) : Wa;   // [k][n]
        __nv_bfloat16* dh = g_Bs + (size_t)(mat * 2 + 0) * 65536;
        __nv_bfloat16* dl = g_Bs + (size_t)(mat * 2 + 1) * 65536;
        #pragma unroll 4
        for (int kp = 0; kp < 16; kp++) {
            int k = kg * 16 + kp;
            float v = W[(size_t)k * 256 + n];
            __nv_bfloat16 h = __float2bfloat16(v);
            dh[(size_t)k * 256 + n] = h;
            dl[(size_t)k * 256 + n] = __float2bfloat16(v - __bfloat162float(h));
        }
        return;
    }
    // patient: proj + LN + head
    int b = blockIdx.x - 32, d = threadIdx.x;
    __shared__ float s_pe[D_], s_p[D_];
    s_pe[d] = pe[b * D_ + d];
    __syncthreads();
    float acc = bp[d];
    #pragma unroll 8
    for (int k = 0; k < D_; k++) acc = fmaf(s_pe[k], Wp[k * D_ + d], acc);
    float s1 = acc, s2 = acc * acc;
    #pragma unroll
    for (int o = 16; o; o >>= 1) {
        s1 += __shfl_xor_sync(0xffffffffu, s1, o);
        s2 += __shfl_xor_sync(0xffffffffu, s2, o);
    }
    __shared__ float r1[8], r2[8], bc[2];
    int w = d >> 5, l = d & 31;
    if (l == 0) { r1[w] = s1; r2[w] = s2; }
    __syncthreads();
    if (d == 0) {
        float t1 = 0.f, t2 = 0.f;
        #pragma unroll
        for (int i = 0; i < 8; i++) { t1 += r1[i]; t2 += r2[i]; }
        float mean = t1 * (1.0f / D_);
        float var  = t2 * (1.0f / D_) - mean * mean;
        bc[0] = mean; bc[1] = rsqrtf(var + EPS_);
    }
    __syncthreads();
    s_p[d] = (acc - bc[0]) * bc[1] * gp[d] + betap[d];
    __syncthreads();
    float acc2 = b1[d];
    #pragma unroll 8
    for (int k = 0; k < D_; k++) acc2 = fmaf(s_p[k], W1[k * H_ + d], acc2);
    g_pht[d * B_ + b] = acc2;
}

// ---------------- fused HMMA kernel (identical to R5) ----------------
static constexpr uint32_t A_HI  = 0;
static constexpr uint32_t A_LO  = 32768;
static constexpr uint32_t B_B0  = 65536;
static constexpr uint32_t B_STR = 16896;
static constexpr uint32_t B_LOO = 8448;
static constexpr uint32_t P_BA  = 99328;
static constexpr uint32_t P_GA  = 100352;
static constexpr uint32_t P_BE  = 101376;
static constexpr uint32_t S_SUM = 102400;
static constexpr uint32_t S_SQ  = 103424;
static constexpr uint32_t S_MRS = 104448;
static constexpr uint32_t SMEM_SZ = 104960;

__global__ __launch_bounds__(256, 2)
void k_fused(const float* __restrict__ atc4,
             const float* __restrict__ ba,
             const float* __restrict__ ga,
             const float* __restrict__ betaa)
{
    extern __shared__ __align__(16) unsigned char smem[];
    uint32_t sb = smem_u32(smem);
    int tid = threadIdx.x;
    int wid = tid >> 5;
    int l   = tid & 31;
    int wm  = wid >> 2;
    int wn  = wid & 3;
    int quad = l >> 2;
    int tid4 = l & 3;
    int m0 = blockIdx.x * 64;

    auto issue = [&](int t) {
        int phase = t >> 4, c = t & 15;
        uint32_t bb = sb + B_B0 + (uint32_t)(t & 1) * B_STR;
        const __nv_bfloat16* bh = g_Bs + (size_t)(phase * 2) * 65536 + (size_t)c * 16 * 256;
        const __nv_bfloat16* bl = bh + 65536;
        #pragma unroll
        for (int it = 0; it < 2; it++) {
            int id = it * 256 + tid;
            int k = id >> 5, u = id & 31;
            uint32_t dst = (uint32_t)k * 528 + (uint32_t)u * 16;
            cp16(bb + dst,         bh + (size_t)k * 256 + u * 8);
            cp16(bb + B_LOO + dst, bl + (size_t)k * 256 + u * 8);
        }
        CP_COMMIT();
    };

    issue(0);
    issue(1);

    ((float*)(smem + P_BA))[tid] = ba[tid];
    ((float*)(smem + P_GA))[tid] = ga[tid];
    ((float*)(smem + P_BE))[tid] = betaa[tid];

    #pragma unroll
    for (int it = 0; it < 8; it++) {
        int id = it * 256 + tid;
        int row = id >> 5, u = id & 31;
        int gr = m0 + row;
        float f[8];
        if (gr < V_) {
            float4 v0 = *(const float4*)&atc4[(size_t)gr * 256 + u * 8];
            float4 v1 = *(const float4*)&atc4[(size_t)gr * 256 + u * 8 + 4];
            f[0]=v0.x; f[1]=v0.y; f[2]=v0.z; f[3]=v0.w;
            f[4]=v1.x; f[5]=v1.y; f[6]=v1.z; f[7]=v1.w;
        } else {
            #pragma unroll
            for (int i = 0; i < 8; i++) f[i] = 0.f;
        }
        float hf[8], lf[8];
        #pragma unroll
        for (int i = 0; i < 8; i++) {
            hf[i] = __bfloat162float(__float2bfloat16(f[i]));
            lf[i] = f[i] - hf[i];
        }
        uint4 hp, lp;
        hp.x = pack2bf16(hf[0], hf[1]); hp.y = pack2bf16(hf[2], hf[3]);
        hp.z = pack2bf16(hf[4], hf[5]); hp.w = pack2bf16(hf[6], hf[7]);
        lp.x = pack2bf16(lf[0], lf[1]); lp.y = pack2bf16(lf[2], lf[3]);
        lp.z = pack2bf16(lf[4], lf[5]); lp.w = pack2bf16(lf[6], lf[7]);
        uint32_t off = (uint32_t)row * 512 + (((uint32_t)u ^ ((uint32_t)row & 7)) << 4);
        *(uint4*)(smem + A_HI + off) = hp;
        *(uint4*)(smem + A_LO + off) = lp;
    }

    int ar = wm * 32 + (l & 15);
    uint32_t arx = (uint32_t)(ar & 7);
    uint32_t a_base = sb + A_HI + (uint32_t)ar * 512;
    uint32_t kusel = (uint32_t)((l >> 4) & 1);
    uint32_t b_lane = (uint32_t)(l & 15) * 528 + (uint32_t)(wn * 64 + ((l >> 4) & 1) * 8) * 2;

    float acc[8][2][4];
    #pragma unroll
    for (int nb = 0; nb < 8; nb++)
        #pragma unroll
        for (int mb = 0; mb < 2; mb++)
            #pragma unroll
            for (int i = 0; i < 4; i++) acc[nb][mb][i] = 0.f;

    #pragma unroll 1
    for (int t = 0; t < 32; t++) {
        int c = t & 15;
        uint32_t bb = sb + B_B0 + (uint32_t)(t & 1) * B_STR;

        if (t == 31) { CP_WAIT(0); } else { CP_WAIT(1); }
        __syncthreads();

        uint32_t ku = (uint32_t)(c * 2) + kusel;
        uint32_t aa = a_base + ((ku ^ arx) << 4);
        uint32_t ah0[4], ah1[4], al0[4], al1[4];
        ldsm4(ah0, aa);
        ldsm4(ah1, aa + 8192);
        ldsm4(al0, aa + 32768);
        ldsm4(al1, aa + 40960);
        #pragma unroll
        for (int p = 0; p < 4; p++) {
            uint32_t bo = bb + b_lane + (uint32_t)(p * 32);
            uint32_t rh[4], rl[4];
            ldsm4t(rh, bo);
            ldsm4t(rl, bo + B_LOO);
            #pragma unroll
            for (int q = 0; q < 2; q++) {
                int nb = p * 2 + q;
                mma_bf16(acc[nb][0], ah0, &rh[q * 2]);
                mma_bf16(acc[nb][0], ah0, &rl[q * 2]);
                mma_bf16(acc[nb][0], al0, &rh[q * 2]);
                mma_bf16(acc[nb][1], ah1, &rh[q * 2]);
                mma_bf16(acc[nb][1], ah1, &rl[q * 2]);
                mma_bf16(acc[nb][1], al1, &rh[q * 2]);
            }
        }

        __syncthreads();
        if (t < 30) issue(t + 2);

        if (t == 15) {
            const float* s_ba = (const float*)(smem + P_BA);
            const float* s_ga = (const float*)(smem + P_GA);
            const float* s_be = (const float*)(smem + P_BE);
            float* psum = (float*)(smem + S_SUM);
            float* psq  = (float*)(smem + S_SQ);
            float* mrs  = (float*)(smem + S_MRS);

            #pragma unroll
            for (int mb = 0; mb < 2; mb++) {
                #pragma unroll
                for (int half = 0; half < 2; half++) {
                    float s1 = 0.f, s2 = 0.f;
                    #pragma unroll
                    for (int nb = 0; nb < 8; nb++) {
                        int col = wn * 64 + nb * 8 + tid4 * 2;
                        float x0 = acc[nb][mb][half * 2 + 0] + s_ba[col];
                        float x1 = acc[nb][mb][half * 2 + 1] + s_ba[col + 1];
                        s1 += x0 + x1;
                        s2 = fmaf(x0, x0, fmaf(x1, x1, s2));
                    }
                    s1 += __shfl_xor_sync(0xffffffffu, s1, 1);
                    s2 += __shfl_xor_sync(0xffffffffu, s2, 1);
                    s1 += __shfl_xor_sync(0xffffffffu, s1, 2);
                    s2 += __shfl_xor_sync(0xffffffffu, s2, 2);
                    if (tid4 == 0) {
                        int row = wm * 32 + mb * 16 + quad + half * 8;
                        psum[row * 4 + wn] = s1;
                        psq[row * 4 + wn]  = s2;
                    }
                }
            }
            __syncthreads();
            if (tid < 64) {
                float s1 = psum[tid * 4] + psum[tid * 4 + 1] + psum[tid * 4 + 2] + psum[tid * 4 + 3];
                float s2 = psq[tid * 4] + psq[tid * 4 + 1] + psq[tid * 4 + 2] + psq[tid * 4 + 3];
                float mean = s1 * (1.0f / 256.0f);
                float var  = s2 * (1.0f / 256.0f) - mean * mean;
                mrs[tid * 2]     = mean;
                mrs[tid * 2 + 1] = rsqrtf(var + EPS_);
            }
            __syncthreads();
            #pragma unroll
            for (int mb = 0; mb < 2; mb++) {
                #pragma unroll
                for (int half = 0; half < 2; half++) {
                    int row = wm * 32 + mb * 16 + quad + half * 8;
                    float mean = mrs[row * 2], rstd = mrs[row * 2 + 1];
                    #pragma unroll
                    for (int nb = 0; nb < 8; nb++) {
                        int col = wn * 64 + nb * 8 + tid4 * 2;
                        float x0 = acc[nb][mb][half * 2 + 0] + s_ba[col];
                        float x1 = acc[nb][mb][half * 2 + 1] + s_ba[col + 1];
                        float v0 = (x0 - mean) * rstd * s_ga[col] + s_be[col];
                        float v1 = (x1 - mean) * rstd * s_ga[col + 1] + s_be[col + 1];
                        float h0 = __bfloat162float(__float2bfloat16(v0));
                        float h1 = __bfloat162float(__float2bfloat16(v1));
                        uint32_t u = (uint32_t)(col >> 3);
                        uint32_t off = (uint32_t)row * 512 + ((u ^ ((uint32_t)row & 7)) << 4)
                                     + (uint32_t)tid4 * 4;
                        *(uint32_t*)(smem + A_HI + off) = pack2bf16(h0, h1);
                        *(uint32_t*)(smem + A_LO + off) = pack2bf16(v0 - h0, v1 - h1);
                    }
                }
            }
            #pragma unroll
            for (int nb = 0; nb < 8; nb++)
                #pragma unroll
                for (int mb = 0; mb < 2; mb++)
                    #pragma unroll
                    for (int i = 0; i < 4; i++) acc[nb][mb][i] = 0.f;
            __syncthreads();
        }

        if (t == 31) {
            #pragma unroll
            for (int mb = 0; mb < 2; mb++) {
                #pragma unroll
                for (int half = 0; half < 2; half++) {
                    int row = wm * 32 + mb * 16 + quad + half * 8;
                    int grow = m0 + row;
                    if (grow < V_) {
                        #pragma unroll
                        for (int nb = 0; nb < 8; nb++) {
                            int col = wn * 64 + nb * 8 + tid4 * 2;
                            float2 o = make_float2(acc[nb][mb][half * 2], acc[nb][mb][half * 2 + 1]);
                            *(float2*)&g_ah[(size_t)grow * 256 + col] = o;
                        }
                    }
                }
            }
        }
    }
}

// ---------------- score: f16x2 tanh, 16 v per block ----------------
__global__ __launch_bounds__(256)
void k_score(const float* __restrict__ W2, const float* __restrict__ b2)
{
    __shared__ uint32_t s_pT[16 * 132];   // [b][h2] half2 pairs (pht[2h],pht[2h+1])
    __shared__ uint32_t s_ah[16 * 128];   // [v][h2] half2 pairs
    __shared__ float4   s_w2[64];

    int t = threadIdx.x;
    int v0 = blockIdx.x * 16;

    // pht -> half2 pairs
    for (int i = t; i < 16 * 128; i += 256) {
        int b = i & 15, h2 = i >> 4;
        float p0 = g_pht[(2 * h2) * 16 + b];
        float p1 = g_pht[(2 * h2 + 1) * 16 + b];
        __half2 h = __floats2half2_rn(p0, p1);
        s_pT[b * 132 + h2] = *(uint32_t*)&h;
    }
    if (t < 64) s_w2[t] = *(const float4*)&W2[t * 4];
    // ah -> half2 pairs
    for (int i = t; i < 16 * 64; i += 256) {
        int r = i >> 6, c4 = i & 63;
        float4 v = *(const float4*)&g_ah[(size_t)(v0 + r) * H_ + c4 * 4];
        __half2 a = __floats2half2_rn(v.x, v.y);
        __half2 c = __floats2half2_rn(v.z, v.w);
        s_ah[r * 128 + c4 * 2]     = *(uint32_t*)&a;
        s_ah[r * 128 + c4 * 2 + 1] = *(uint32_t*)&c;
    }
    __syncthreads();

    int w = t >> 5, lane = t & 31;
    int b = lane & 15;
    int vloc = w * 2 + (lane >> 4);

    const uint4* arow = (const uint4*)&s_ah[vloc * 128];
    const uint4* prow = (const uint4*)&s_pT[b * 132];
    float acc = b2[0];
    #pragma unroll 8
    for (int u = 0; u < 32; u++) {       // 8 h per iteration
        uint4 a4 = arow[u];
        uint4 p4 = prow[u];
        float4 w0 = s_w2[u * 2];
        float4 w1 = s_w2[u * 2 + 1];
        uint32_t x0, x1, x2, x3;
        asm("add.rn.f16x2 %0, %1, %2;" : "=r"(x0) : "r"(a4.x), "r"(p4.x));
        asm("add.rn.f16x2 %0, %1, %2;" : "=r"(x1) : "r"(a4.y), "r"(p4.y));
        asm("add.rn.f16x2 %0, %1, %2;" : "=r"(x2) : "r"(a4.z), "r"(p4.z));
        asm("add.rn.f16x2 %0, %1, %2;" : "=r"(x3) : "r"(a4.w), "r"(p4.w));
        asm("tanh.approx.f16x2 %0, %1;" : "=r"(x0) : "r"(x0));
        asm("tanh.approx.f16x2 %0, %1;" : "=r"(x1) : "r"(x1));
        asm("tanh.approx.f16x2 %0, %1;" : "=r"(x2) : "r"(x2));
        asm("tanh.approx.f16x2 %0, %1;" : "=r"(x3) : "r"(x3));
        float2 f0 = __half22float2(*(__half2*)&x0);
        float2 f1 = __half22float2(*(__half2*)&x1);
        float2 f2 = __half22float2(*(__half2*)&x2);
        float2 f3 = __half22float2(*(__half2*)&x3);
        acc = fmaf(w0.x, f0.x, acc); acc = fmaf(w0.y, f0.y, acc);
        acc = fmaf(w0.z, f1.x, acc); acc = fmaf(w0.w, f1.y, acc);
        acc = fmaf(w1.x, f2.x, acc); acc = fmaf(w1.y, f2.y, acc);
        acc = fmaf(w1.z, f3.x, acc); acc = fmaf(w1.w, f3.y, acc);
    }
    g_scores[(size_t)b * V_ + v0 + vloc] = acc;
}

// ---------------- per-b mean/rstd over V ----------------
__global__ __launch_bounds__(1024)
void k_reduce()
{
    int b = blockIdx.x, t = threadIdx.x;
    const float4* row = (const float4*)&g_scores[(size_t)b * V_];
    float s1 = 0.f, s2 = 0.f;
    #pragma unroll
    for (int v = t; v < V_ / 4; v += 1024) {
        float4 x = row[v];
        s1 += x.x + x.y + x.z + x.w;
        s2 = fmaf(x.x, x.x, fmaf(x.y, x.y, fmaf(x.z, x.z, fmaf(x.w, x.w, s2))));
    }
    #pragma unroll
    for (int o = 16; o; o >>= 1) {
        s1 += __shfl_xor_sync(0xffffffffu, s1, o);
        s2 += __shfl_xor_sync(0xffffffffu, s2, o);
    }
    __shared__ float r1[32], r2[32];
    int w = t >> 5, ll = t & 31;
    if (ll == 0) { r1[w] = s1; r2[w] = s2; }
    __syncthreads();
    if (t < 32) {
        float a1 = r1[t], a2 = r2[t];
        #pragma unroll
        for (int o = 16; o; o >>= 1) {
            a1 += __shfl_xor_sync(0xffffffffu, a1, o);
            a2 += __shfl_xor_sync(0xffffffffu, a2, o);
        }
        if (t == 0) {
            float mean = a1 * (1.0f / V_);
            float var  = a2 * (1.0f / V_) - mean * mean;
            g_stats[2 * b] = mean;
            g_stats[2 * b + 1] = rsqrtf(var + EPS_);
        }
    }
}

__global__ void k_norm(const float* __restrict__ g_pred,
                       const float* __restrict__ b_pred,
                       float* __restrict__ out)
{
    int i = blockIdx.x * 256 + threadIdx.x;
    if (i >= B_ * V_) return;
    int b = i / V_;
    int v = i - b * V_;
    out[i] = (g_scores[i] - g_stats[2 * b]) * g_stats[2 * b + 1] * g_pred[v] + b_pred[v];
}

// ---------------- launch ----------------
extern "C" void kernel_launch(void* const* d_in, const int* in_sizes, int n_in,
                              void* d_out, int out_size)
{
    const float* pe     = (const float*)d_in[0];
    const float* atc4   = (const float*)d_in[1];
    const float* Wp     = (const float*)d_in[2];
    const float* bp     = (const float*)d_in[3];
    const float* gp     = (const float*)d_in[4];
    const float* betap  = (const float*)d_in[5];
    const float* Wa     = (const float*)d_in[6];
    const float* ba     = (const float*)d_in[7];
    const float* ga     = (const float*)d_in[8];
    const float* betaa  = (const float*)d_in[9];
    const float* W1     = (const float*)d_in[10];
    const float* b1     = (const float*)d_in[11];
    const float* W2     = (const float*)d_in[12];
    const float* b2     = (const float*)d_in[13];
    const float* gpred  = (const float*)d_in[14];
    const float* bpred  = (const float*)d_in[15];
    float* out = (float*)d_out;
    (void)in_sizes; (void)n_in; (void)out_size;

    cudaFuncSetAttribute(k_fused, cudaFuncAttributeMaxDynamicSharedMemorySize, SMEM_SZ);

    k_prep<<<48, 256>>>(Wa, W1, pe, Wp, bp, gp, betap, b1);

    int tiles = (V_ + 63) / 64;   // 313
    k_fused<<<tiles, 256, SMEM_SZ>>>(atc4, ba, ga, betaa);

    k_score<<<V_ / 16, 256>>>(W2, b2);
    k_reduce<<<B_, 1024>>>();
    k_norm<<<(B_ * V_ + 255) / 256, 256>>>(gpred, bpred, out);
}